// round 9
// baseline (speedup 1.0000x reference)
#include <cuda_runtime.h>

#define TT 2048
#define DD 64
#define HH 64
#define NG 256          // 4*H gates
#define WPAD 68         // padded W_ih row stride (floats), 272B = 16B-aligned

// SMEM float offsets
#define WS_OFF   0                      // W_ih staged: [256][WPAD]
#define XG_OFF   (256 * WPAD)           // xg ring:    [2][16][256]
#define XR_OFF   (XG_OFF + 2*16*256)    // x ring:     [2][32][64]
#define HS_OFF   (XR_OFF + 2*32*64)     // h dbl-buf:  [2][2][64]
#define SMEM_FLOATS (HS_OFF + 2*2*64)
#define SMEM_BYTES  (SMEM_FLOATS * 4)   // 119,808 B

// Packed fp32x2 FMA (sm_100+)
__device__ __forceinline__ unsigned long long ffma2(unsigned long long a,
                                                    unsigned long long b,
                                                    unsigned long long c) {
    unsigned long long d;
    asm("fma.rn.f32x2 %0, %1, %2, %3;" : "=l"(d) : "l"(a), "l"(b), "l"(c));
    return d;
}
__device__ __forceinline__ float red2(unsigned long long v) {
    float lo, hi;
    asm("mov.b64 {%0, %1}, %2;" : "=f"(lo), "=f"(hi) : "l"(v));
    return lo + hi;
}
__device__ __forceinline__ float tanh_ap(float x) {
    float y;
    asm("tanh.approx.f32 %0, %1;" : "=f"(y) : "f"(x));
    return y;
}

// ---------------------------------------------------------------------------
// Fused kernel: grid=128, 512... no: 256 threads = 2 groups x 128 (1 batch
// each, own named barrier). Thread pair (lane, lane^1): role0 owns (i_u,g_u),
// role1 owns (f_u,o_u); W_hh rows register-resident.
// Producer side (same threads, fills idle issue slots): computes xg =
// bias + W_ih . x for 8 future steps at a time, one k-chunk per step,
// W_ih from SMEM, x from a GMEM->SMEM ring staged 18 steps ahead.
// One named barrier per step orders h, xg-ring, and x-ring handoffs.
// ---------------------------------------------------------------------------
__global__ void __launch_bounds__(256, 1)
lstm_fused(const float* __restrict__ x, const float* __restrict__ w_ih,
           const float* __restrict__ w_hh, const float* __restrict__ b_ih,
           const float* __restrict__ b_hh, const float* __restrict__ fc_w,
           const float* __restrict__ fc_b, float* __restrict__ out, int Tn)
{
    extern __shared__ __align__(16) float sm[];
    float* Ws = sm + WS_OFF;                 // [256][WPAD]
    float* XG = sm + XG_OFF;                 // [grp][16][256]
    float* XR = sm + XR_OFF;                 // [grp][32][64]
    float* HS = sm + HS_OFF;                 // [grp][2][64]

    const int tid  = threadIdx.x;
    const int grp  = tid >> 7;
    const int lt   = tid & 127;
    const int u    = lt >> 1;
    const int role = lt & 1;                 // 0:(i,g)  1:(f,o)
    const int ga   = u + 64 * role;
    const int gb   = ga + 128;
    const int b    = blockIdx.x * 2 + grp;
    const int barid = grp + 1;

    float* xgg = XG + grp * (16 * 256);
    float* xrg = XR + grp * (32 * 64);
    float* hsg = HS + grp * 128;

    // ---- register-resident W_hh rows ----
    ulonglong2 wa[16], wb[16];
    {
        const ulonglong2* pwa = (const ulonglong2*)(w_hh + ga * HH);
        const ulonglong2* pwb = (const ulonglong2*)(w_hh + gb * HH);
#pragma unroll
        for (int j = 0; j < 16; ++j) { wa[j] = pwa[j]; wb[j] = pwb[j]; }
    }
    const float ba = b_ih[ga] + b_hh[ga];
    const float bb = b_ih[gb] + b_hh[gb];

    // ---- stage W_ih into padded SMEM (thread tid owns row tid) ----
    {
        const float4* src = (const float4*)(w_ih + tid * DD);
        float4* dst = (float4*)(Ws + tid * WPAD);
#pragma unroll
        for (int q = 0; q < 16; ++q) dst[q] = src[q];
    }

    // ---- stage x[0..18) into the ring; prime the 2-deep LDG pipeline ----
    const float* xb = x + (size_t)b * Tn * DD;
    for (int idx = lt; idx < 18 * 16; idx += 128) {
        int slot = idx >> 4, q = idx & 15;
        ((float4*)(xrg + slot * 64))[q] = ((const float4*)(xb + slot * DD))[q];
    }
    float4 preP = make_float4(0.f, 0.f, 0.f, 0.f), preN = preP;
    if (lt < 16) {
        preP = ((const float4*)(xb + 18 * DD))[lt];
        preN = ((const float4*)(xb + 19 * DD))[lt];
    }
    if (lt < 64) { hsg[lt] = 0.f; hsg[64 + lt] = 0.f; }
    __syncthreads();

    // ---- gemm accumulators: 8 future t x 2 gates, packed (even,odd) k ----
    unsigned long long aca[8], acb[8];
#pragma unroll
    for (int i = 0; i < 8; ++i) { aca[i] = 0ull; acb[i] = 0ull; }

    // ---- prologue window: compute xg[0..8) from x slots 0..7 ----
    const float* wra = Ws + ga * WPAD;
    const float* wrb = Ws + gb * WPAD;
#pragma unroll
    for (int s = 0; s < 8; ++s) {
        ulonglong2 wc0 = *(const ulonglong2*)(wra + 8 * s);
        ulonglong2 wc1 = *(const ulonglong2*)(wra + 8 * s + 4);
        ulonglong2 vc0 = *(const ulonglong2*)(wrb + 8 * s);
        ulonglong2 vc1 = *(const ulonglong2*)(wrb + 8 * s + 4);
#pragma unroll
        for (int i = 0; i < 8; ++i) {
            ulonglong2 x0 = *(const ulonglong2*)(xrg + i * 64 + 8 * s);
            ulonglong2 x1 = *(const ulonglong2*)(xrg + i * 64 + 8 * s + 4);
            aca[i] = ffma2(wc0.x, x0.x, aca[i]);
            aca[i] = ffma2(wc0.y, x0.y, aca[i]);
            aca[i] = ffma2(wc1.x, x1.x, aca[i]);
            aca[i] = ffma2(wc1.y, x1.y, aca[i]);
            acb[i] = ffma2(vc0.x, x0.x, acb[i]);
            acb[i] = ffma2(vc0.y, x0.y, acb[i]);
            acb[i] = ffma2(vc1.x, x1.x, acb[i]);
            acb[i] = ffma2(vc1.y, x1.y, acb[i]);
        }
    }
#pragma unroll
    for (int i = 0; i < 8; ++i) {
        xgg[i * 256 + ga] = ba + red2(aca[i]);
        xgg[i * 256 + gb] = bb + red2(acb[i]);
        aca[i] = 0ull; acb[i] = 0ull;
    }
    __syncthreads();

    // Bv activation constants: role0 -> tanh; role1 -> sigmoid
    const float kb  = role ? 0.5f : 1.f;
    const float sc  = role ? 0.5f : 1.f;
    const float off = role ? 0.5f : 0.f;

    float c = 0.f;   // redundant cell state on both roles

    for (int t = 0; t < Tn; ++t) {
        const int s = t & 7;

        // -------- recurrence (consumes xg ring slot t%16) --------
        float xa0 = xgg[(t & 15) * 256 + ga];
        float xb0 = xgg[(t & 15) * 256 + gb];

        const ulonglong2* hv = (const ulonglong2*)(hsg + (t & 1) * 64);
        unsigned long long a0 = 0ull, a1 = 0ull, c0 = 0ull, c1 = 0ull;
#pragma unroll
        for (int j = 0; j < 16; ++j) {
            ulonglong2 h2 = hv[j];
            a0 = ffma2(wa[j].x, h2.x, a0);
            a1 = ffma2(wa[j].y, h2.y, a1);
            c0 = ffma2(wb[j].x, h2.x, c0);
            c1 = ffma2(wb[j].y, h2.y, c1);
        }
        float sa = xa0 + red2(a0) + red2(a1);
        float sb = xb0 + red2(c0) + red2(c1);

        float A  = fmaf(0.5f, tanh_ap(0.5f * sa), 0.5f);   // i or f
        float Bv = fmaf(sc, tanh_ap(kb * sb), off);        // g or o
        float p  = A * Bv;
        float send = role ? A : p;
        float recv = __shfl_xor_sync(0xFFFFFFFFu, send, 1);
        float cmul = role ? A : recv;
        float cadd = role ? recv : p;
        c = fmaf(cmul, c, cadd);
        float th = tanh_ap(c);
        if (role) hsg[128 + ((t + 1) & 1) * 64 - 128 + u + ((t + 1) & 1) * 0] = 0.f; // placeholder removed below
        if (role) hsg[((t + 1) & 1) * 64 + u] = Bv * th;   // h = o * tanh(c)

        // -------- producer: k-chunk s of window xg[t-s+8 .. t-s+16) --------
        {
            const int twbase = (t - s) + 8;
            ulonglong2 wc0 = *(const ulonglong2*)(wra + 8 * s);
            ulonglong2 wc1 = *(const ulonglong2*)(wra + 8 * s + 4);
            ulonglong2 vc0 = *(const ulonglong2*)(wrb + 8 * s);
            ulonglong2 vc1 = *(const ulonglong2*)(wrb + 8 * s + 4);
#pragma unroll
            for (int i = 0; i < 8; ++i) {
                const float* xs = xrg + ((twbase + i) & 31) * 64 + 8 * s;
                ulonglong2 x0 = *(const ulonglong2*)xs;
                ulonglong2 x1 = *(const ulonglong2*)(xs + 4);
                aca[i] = ffma2(wc0.x, x0.x, aca[i]);
                aca[i] = ffma2(wc0.y, x0.y, aca[i]);
                aca[i] = ffma2(wc1.x, x1.x, aca[i]);
                aca[i] = ffma2(wc1.y, x1.y, aca[i]);
                acb[i] = ffma2(vc0.x, x0.x, acb[i]);
                acb[i] = ffma2(vc0.y, x0.y, acb[i]);
                acb[i] = ffma2(vc1.x, x1.x, acb[i]);
                acb[i] = ffma2(vc1.y, x1.y, acb[i]);
            }
            if (s == 7) {   // finalize window into xg ring, reset accs
#pragma unroll
                for (int i = 0; i < 8; ++i) {
                    xgg[((twbase + i) & 15) * 256 + ga] = ba + red2(aca[i]);
                    xgg[((twbase + i) & 15) * 256 + gb] = bb + red2(acb[i]);
                    aca[i] = 0ull; acb[i] = 0ull;
                }
            }
        }

        // -------- x staging: STS slot t+18, LDG t+20 (2-deep pipeline) ----
        if (lt < 16) {
            ((float4*)(xrg + ((t + 18) & 31) * 64))[lt] = preP;
            preP = preN;
            if (t + 20 < Tn)
                preN = ((const float4*)(xb + (size_t)(t + 20) * DD))[lt];
        }

        asm volatile("bar.sync %0, 128;" :: "r"(barid));
    }

    // ---- final FC: out[b, o] = h_last . fc_w[o] + fc_b[o] ----
    const float* hfin = hsg + (Tn & 1) * 64;
    if (lt < 8) {
        float s = fc_b[lt];
#pragma unroll
        for (int k = 0; k < HH; ++k) s += hfin[k] * fc_w[lt * HH + k];
        out[b * 8 + lt] = s;
    }
}

extern "C" void kernel_launch(void* const* d_in, const int* in_sizes, int n_in,
                              void* d_out, int out_size) {
    const float* x    = (const float*)d_in[0];
    const float* w_ih = (const float*)d_in[1];
    const float* w_hh = (const float*)d_in[2];
    const float* b_ih = (const float*)d_in[3];
    const float* b_hh = (const float*)d_in[4];
    const float* fc_w = (const float*)d_in[5];
    const float* fc_b = (const float*)d_in[6];
    float* out = (float*)d_out;

    const int B = in_sizes[0] / (TT * DD);   // 256

    static int attr_done = 0;
    if (!attr_done) {
        cudaFuncSetAttribute(lstm_fused,
                             cudaFuncAttributeMaxDynamicSharedMemorySize,
                             SMEM_BYTES);
        attr_done = 1;
    }
    lstm_fused<<<B / 2, 256, SMEM_BYTES>>>(x, w_ih, w_hh, b_ih, b_hh,
                                           fc_w, fc_b, out, TT);
}

// round 10
// speedup vs baseline: 1.1160x; 1.1160x over previous
#include <cuda_runtime.h>

#define TT 2048
#define DD 64
#define HH 64
#define NG 256   // 4*H gates
#define BB_TOT 256

// 512 MB scratch: precomputed input projections xg[b][t][g] (bias included)
__device__ float g_xg[(size_t)BB_TOT * TT * NG];

// Packed fp32x2 FMA (sm_100+): d = a*b + c on two packed floats.
__device__ __forceinline__ unsigned long long ffma2(unsigned long long a,
                                                    unsigned long long b,
                                                    unsigned long long c) {
    unsigned long long d;
    asm("fma.rn.f32x2 %0, %1, %2, %3;" : "=l"(d) : "l"(a), "l"(b), "l"(c));
    return d;
}
__device__ __forceinline__ float red2(unsigned long long v) {
    float lo, hi;
    asm("mov.b64 {%0, %1}, %2;" : "=f"(lo), "=f"(hi) : "l"(v));
    return lo + hi;
}
// HW tanh: single MUFU op (sm_75+), ~16 cyc
__device__ __forceinline__ float tanh_ap(float x) {
    float y;
    asm("tanh.approx.f32 %0, %1;" : "=f"(y) : "f"(x));
    return y;
}

// ---------------------------------------------------------------------------
// Kernel 1 (unchanged from R6, measured ~380us): xg = bias + W_ih . x
// ---------------------------------------------------------------------------
__global__ void __launch_bounds__(256, 1)
xg_gemm(const float* __restrict__ x, const float* __restrict__ w_ih,
        const float* __restrict__ b_ih, const float* __restrict__ b_hh,
        int nrows)
{
    __shared__ __align__(16) float xs[2][32][DD];   // 2 x 8KB tiles

    const int tid  = threadIdx.x;
    const int tg   = tid & 127;       // gate pair: gates 2tg, 2tg+1
    const int half = tid >> 7;        // rows 0..15 or 16..31
    const int g0   = 2 * tg;

    ulonglong2 wa[16], wb[16];
    {
        const ulonglong2* pa = (const ulonglong2*)(w_ih + (size_t)g0 * DD);
        const ulonglong2* pb = (const ulonglong2*)(w_ih + (size_t)(g0 + 1) * DD);
#pragma unroll
        for (int j = 0; j < 16; ++j) { wa[j] = pa[j]; wb[j] = pb[j]; }
    }
    const float ba = b_ih[g0] + b_hh[g0];
    const float bb = b_ih[g0 + 1] + b_hh[g0 + 1];

    const int ntiles = nrows / 32;
    int tile = blockIdx.x;
    int buf = 0;

    float4 pre0 = make_float4(0.f, 0.f, 0.f, 0.f), pre1 = pre0;
    if (tile < ntiles) {
        const float4* src = (const float4*)(x + (size_t)tile * 32 * DD);
        pre0 = src[tid]; pre1 = src[tid + 256];
    }

    while (tile < ntiles) {
        ((float4*)xs[buf])[tid] = pre0;
        ((float4*)xs[buf])[tid + 256] = pre1;
        __syncthreads();

        int next = tile + gridDim.x;
        if (next < ntiles) {
            const float4* src = (const float4*)(x + (size_t)next * 32 * DD);
            pre0 = src[tid]; pre1 = src[tid + 256];
        }

        float* dst = g_xg + ((size_t)tile * 32 + half * 16) * NG + g0;
#pragma unroll 2
        for (int r = 0; r < 16; ++r) {
            const ulonglong2* v = (const ulonglong2*)xs[buf][half * 16 + r];
            unsigned long long a0 = 0ull, a1 = 0ull, c0 = 0ull, c1 = 0ull;
#pragma unroll
            for (int j = 0; j < 16; ++j) {
                ulonglong2 h2 = v[j];
                a0 = ffma2(wa[j].x, h2.x, a0);
                a1 = ffma2(wa[j].y, h2.y, a1);
                c0 = ffma2(wb[j].x, h2.x, c0);
                c1 = ffma2(wb[j].y, h2.y, c1);
            }
            *(float2*)(dst + r * NG) =
                make_float2(ba + red2(a0) + red2(a1), bb + red2(c0) + red2(c1));
        }
        buf ^= 1;
        tile = next;
    }
}

// ---------------------------------------------------------------------------
// Kernel 2: recurrence. grid=128, block=128 threads, TWO batches per block.
// Thread pair (lane, lane^1): role0 owns gates (i_u,g_u), role1 (f_u,o_u);
// each thread evaluates BOTH batches with the SAME register-resident W_hh
// rows (weights amortized; 8 independent FFMA2 chains = in-warp ILP).
// Cell update via one shfl.xor per batch. h double-buffered; ONE
// __syncthreads per step. All activations via MUFU tanh.approx.
// ---------------------------------------------------------------------------
__global__ void __launch_bounds__(128, 1)
lstm_rec(const float* __restrict__ w_hh, const float* __restrict__ fc_w,
         const float* __restrict__ fc_b, float* __restrict__ out, int Tn)
{
    __shared__ __align__(16) float hsm[2][2][HH];   // [buf][batch][unit]

    const int tid  = threadIdx.x;       // 0..127
    const int u    = tid >> 1;          // unit 0..63
    const int role = tid & 1;           // 0: (i,g)   1: (f,o)
    const int ga   = u + 64 * role;     // i_u or f_u
    const int gb   = ga + 128;          // g_u or o_u
    const int b0   = blockIdx.x * 2;

    ulonglong2 wa[16], wb[16];
    {
        const ulonglong2* pwa = (const ulonglong2*)(w_hh + ga * HH);
        const ulonglong2* pwb = (const ulonglong2*)(w_hh + gb * HH);
#pragma unroll
        for (int j = 0; j < 16; ++j) { wa[j] = pwa[j]; wb[j] = pwb[j]; }
    }

    // Bv activation: role0 -> tanh(sb); role1 -> sigm(sb)=0.5*tanh(0.5 sb)+0.5
    const float kb  = role ? 0.5f : 1.f;
    const float sc  = role ? 0.5f : 1.f;
    const float off = role ? 0.5f : 0.f;

    const float* p0 = g_xg + (size_t)b0 * Tn * NG + ga;        // batch 0
    const float* p1 = g_xg + (size_t)(b0 + 1) * Tn * NG + ga;  // batch 1

    // prefetch pipeline, distance 4, per batch per gate
    float xa0_0 = p0[0],      xb0_0 = p0[128];
    float xa1_0 = p0[NG],     xb1_0 = p0[NG + 128];
    float xa2_0 = p0[2 * NG], xb2_0 = p0[2 * NG + 128];
    float xa3_0 = p0[3 * NG], xb3_0 = p0[3 * NG + 128];
    float xa0_1 = p1[0],      xb0_1 = p1[128];
    float xa1_1 = p1[NG],     xb1_1 = p1[NG + 128];
    float xa2_1 = p1[2 * NG], xb2_1 = p1[2 * NG + 128];
    float xa3_1 = p1[3 * NG], xb3_1 = p1[3 * NG + 128];
    p0 += 4 * NG; p1 += 4 * NG;

    if (tid < 64) {
        hsm[0][0][tid] = 0.f; hsm[0][1][tid] = 0.f;
        hsm[1][0][tid] = 0.f; hsm[1][1][tid] = 0.f;
    }
    __syncthreads();

    float c0s = 0.f, c1s = 0.f;   // cell states (redundant on both roles)

    for (int t = 0; t < Tn; ++t) {
        const ulonglong2* hv0 = (const ulonglong2*)hsm[t & 1][0];
        const ulonglong2* hv1 = (const ulonglong2*)hsm[t & 1][1];
        unsigned long long A0 = 0ull, A1 = 0ull, C0 = 0ull, C1 = 0ull;
        unsigned long long D0 = 0ull, D1 = 0ull, E0 = 0ull, E1 = 0ull;
#pragma unroll
        for (int j = 0; j < 16; ++j) {
            ulonglong2 h20 = hv0[j];
            ulonglong2 h21 = hv1[j];
            A0 = ffma2(wa[j].x, h20.x, A0);
            A1 = ffma2(wa[j].y, h20.y, A1);
            C0 = ffma2(wb[j].x, h20.x, C0);
            C1 = ffma2(wb[j].y, h20.y, C1);
            D0 = ffma2(wa[j].x, h21.x, D0);
            D1 = ffma2(wa[j].y, h21.y, D1);
            E0 = ffma2(wb[j].x, h21.x, E0);
            E1 = ffma2(wb[j].y, h21.y, E1);
        }
        float sa0 = xa0_0 + red2(A0) + red2(A1);
        float sb0 = xb0_0 + red2(C0) + red2(C1);
        float sa1 = xa0_1 + red2(D0) + red2(D1);
        float sb1 = xb0_1 + red2(E0) + red2(E1);

        // rotate prefetch; LDGs overlap the epilogue
        xa0_0 = xa1_0; xa1_0 = xa2_0; xa2_0 = xa3_0;
        xb0_0 = xb1_0; xb1_0 = xb2_0; xb2_0 = xb3_0;
        xa0_1 = xa1_1; xa1_1 = xa2_1; xa2_1 = xa3_1;
        xb0_1 = xb1_1; xb1_1 = xb2_1; xb2_1 = xb3_1;
        if (t + 4 < Tn) {
            xa3_0 = p0[0]; xb3_0 = p0[128];
            xa3_1 = p1[0]; xb3_1 = p1[128];
            p0 += NG; p1 += NG;
        }

        // ---- epilogue, batch 0 ----
        float Aq0  = fmaf(0.5f, tanh_ap(0.5f * sa0), 0.5f);  // i or f
        float Bv0  = fmaf(sc, tanh_ap(kb * sb0), off);       // g or o
        float pr0  = Aq0 * Bv0;
        float sd0  = role ? Aq0 : pr0;
        // ---- epilogue, batch 1 (independent; interleaves with batch 0) ----
        float Aq1  = fmaf(0.5f, tanh_ap(0.5f * sa1), 0.5f);
        float Bv1  = fmaf(sc, tanh_ap(kb * sb1), off);
        float pr1  = Aq1 * Bv1;
        float sd1  = role ? Aq1 : pr1;

        float rv0 = __shfl_xor_sync(0xFFFFFFFFu, sd0, 1);
        float rv1 = __shfl_xor_sync(0xFFFFFFFFu, sd1, 1);

        float cm0 = role ? Aq0 : rv0, cd0 = role ? rv0 : pr0;
        float cm1 = role ? Aq1 : rv1, cd1 = role ? rv1 : pr1;
        c0s = fmaf(cm0, c0s, cd0);
        c1s = fmaf(cm1, c1s, cd1);
        float th0 = tanh_ap(c0s);
        float th1 = tanh_ap(c1s);
        if (role) {
            hsm[(t + 1) & 1][0][u] = Bv0 * th0;   // h = o * tanh(c)
            hsm[(t + 1) & 1][1][u] = Bv1 * th1;
        }
        __syncthreads();
    }

    // final FC: out[b, o] = h_last . fc_w[o] + fc_b[o]
    if (tid < 16) {
        int bb = tid >> 3, o = tid & 7;
        const float* hfin = hsm[Tn & 1][bb];
        float s = fc_b[o];
#pragma unroll
        for (int k = 0; k < HH; ++k) s += hfin[k] * fc_w[o * HH + k];
        out[(b0 + bb) * 8 + o] = s;
    }
}

extern "C" void kernel_launch(void* const* d_in, const int* in_sizes, int n_in,
                              void* d_out, int out_size) {
    const float* x    = (const float*)d_in[0];
    const float* w_ih = (const float*)d_in[1];
    const float* w_hh = (const float*)d_in[2];
    const float* b_ih = (const float*)d_in[3];
    const float* b_hh = (const float*)d_in[4];
    const float* fc_w = (const float*)d_in[5];
    const float* fc_b = (const float*)d_in[6];
    float* out = (float*)d_out;

    const int B = in_sizes[0] / (TT * DD);   // 256
    const int nrows = B * TT;

    xg_gemm<<<148, 256>>>(x, w_ih, b_ih, b_hh, nrows);
    lstm_rec<<<B / 2, 128>>>(w_hh, fc_w, fc_b, out, TT);
}

// round 12
// speedup vs baseline: 1.2854x; 1.1518x over previous
#include <cuda_runtime.h>

#define TT   2048
#define DD   64
#define HH   64
#define NG   256
#define WIN  8                 // steps per window
#define NWINS (TT / WIN)       // 256
#define RING 32                // xg ring slots (4 windows)

// Dynamic SMEM layout (floats):
//  XGR: [2][RING][NG]      = 2*32*256 = 16384   xg ring per batch
//  XST: [4][2][WIN][DD]    = 4*2*8*64 = 4096    x stage ring (4 windows)
//  HS : [2][2][HH]         = 256               h double buffer
#define XGR_OFF 0
#define XST_OFF 16384
#define HS_OFF  (16384 + 4096)
#define SMEM_FLOATS (HS_OFF + 256)
#define SMEM_BYTES  (SMEM_FLOATS * 4)   // 82,944 B

__device__ __forceinline__ unsigned long long ffma2(unsigned long long a,
                                                    unsigned long long b,
                                                    unsigned long long c) {
    unsigned long long d;
    asm("fma.rn.f32x2 %0, %1, %2, %3;" : "=l"(d) : "l"(a), "l"(b), "l"(c));
    return d;
}
__device__ __forceinline__ float red2(unsigned long long v) {
    float lo, hi;
    asm("mov.b64 {%0, %1}, %2;" : "=f"(lo), "=f"(hi) : "l"(v));
    return lo + hi;
}
__device__ __forceinline__ float tanh_ap(float x) {
    float y;
    asm("tanh.approx.f32 %0, %1;" : "=f"(y) : "f"(x));
    return y;
}

// ---------------------------------------------------------------------------
// One fused kernel. grid=128, block=256.
//   warps 0-3  (tid 0..127): recurrence for 2 batches (R10 structure),
//                            xg read from SMEM ring, bar.sync 1,128 per step.
//   warps 4-7  (tid 128..255): producer — xg = bias + W_ih . x for the same
//                            2 batches, computed 3 windows (24 steps) ahead
//                            into the ring; x staged GMEM->SMEM 4 windows ahead.
//   __syncthreads() once per 8-step window joins the two sides.
// ---------------------------------------------------------------------------
__global__ void __launch_bounds__(256, 1)
lstm_ws(const float* __restrict__ x, const float* __restrict__ w_ih,
        const float* __restrict__ w_hh, const float* __restrict__ b_ih,
        const float* __restrict__ b_hh, const float* __restrict__ fc_w,
        const float* __restrict__ fc_b, float* __restrict__ out)
{
    extern __shared__ __align__(16) float sm[];
    float* XGR = sm + XGR_OFF;   // [bb][slot][gate]
    float* XST = sm + XST_OFF;   // [sslot][bb][t'][k]
    float* HS  = sm + HS_OFF;    // [buf][bb][u]

    const int tid = threadIdx.x;
    const int b0  = blockIdx.x * 2;
    const bool is_rec = (tid < 128);

    // ---------- prologue: cooperatively stage x windows 0..3 ----------
    {
#pragma unroll
        for (int r = 0; r < 4; ++r) {
            int idx = tid + r * 256;            // 0..1023 float4s
            int win = idx >> 8;                 // window 0..3
            int wi  = idx & 255;                // within-window float4
            int bb  = wi >> 7;
            int rem = wi & 127;
            int tq  = rem >> 4;                 // t' 0..7
            int q   = rem & 15;                 // k-quarter
            float4 v = ((const float4*)(x +
                        ((size_t)(b0 + bb) * TT + win * WIN + tq) * DD))[q];
            ((float4*)(XST + win * (2 * WIN * DD)))[wi] = v;
        }
    }
    __syncthreads();

    // =====================  REC side state  =====================
    int u = 0, role = 0, ga = 0, gb = 0;
    ulonglong2 wa[16], wb[16];
    float kb = 0.f, sc = 0.f, off = 0.f;
    // =====================  PROD side state =====================
    int pt = tid - 128;
    int pga = pt, pgb = pt + 128;
    ulonglong2 wpa[16], wpb[16];
    float bpa = 0.f, bpb = 0.f;

    if (is_rec) {
        u = tid >> 1; role = tid & 1;
        ga = u + 64 * role; gb = ga + 128;
        const ulonglong2* pwa = (const ulonglong2*)(w_hh + ga * HH);
        const ulonglong2* pwb = (const ulonglong2*)(w_hh + gb * HH);
#pragma unroll
        for (int j = 0; j < 16; ++j) { wa[j] = pwa[j]; wb[j] = pwb[j]; }
        kb  = role ? 0.5f : 1.f;
        sc  = role ? 0.5f : 1.f;
        off = role ? 0.5f : 0.f;
        if (tid < 64) {
            HS[tid] = 0.f; HS[64 + tid] = 0.f;
            HS[128 + tid] = 0.f; HS[192 + tid] = 0.f;
        }
    } else {
        const ulonglong2* pa = (const ulonglong2*)(w_ih + (size_t)pga * DD);
        const ulonglong2* pb = (const ulonglong2*)(w_ih + (size_t)pgb * DD);
#pragma unroll
        for (int j = 0; j < 16; ++j) { wpa[j] = pa[j]; wpb[j] = pb[j]; }
        bpa = b_ih[pga] + b_hh[pga];
        bpb = b_ih[pgb] + b_hh[pgb];

        // prologue: compute windows 0,1,2 into the xg ring
        for (int wc = 0; wc < 3; ++wc) {
            const float* xw = XST + (wc & 3) * (2 * WIN * DD);
#pragma unroll
            for (int bb = 0; bb < 2; ++bb) {
                unsigned long long aa[8], ab[8];
#pragma unroll
                for (int i = 0; i < 8; ++i) { aa[i] = 0ull; ab[i] = 0ull; }
#pragma unroll
                for (int j = 0; j < 16; ++j) {
                    ulonglong2 wja = wpa[j], wjb = wpb[j];
#pragma unroll
                    for (int i = 0; i < 8; ++i) {
                        ulonglong2 xv = *(const ulonglong2*)(xw + bb * WIN * DD
                                                             + i * DD + j * 4);
                        aa[i] = ffma2(wja.x, xv.x, aa[i]);
                        aa[i] = ffma2(wja.y, xv.y, aa[i]);
                        ab[i] = ffma2(wjb.x, xv.x, ab[i]);
                        ab[i] = ffma2(wjb.y, xv.y, ab[i]);
                    }
                }
#pragma unroll
                for (int i = 0; i < 8; ++i) {
                    int slot = (wc * WIN + i) & (RING - 1);
                    XGR[bb * (RING * NG) + slot * NG + pga] = bpa + red2(aa[i]);
                    XGR[bb * (RING * NG) + slot * NG + pgb] = bpb + red2(ab[i]);
                }
            }
        }
    }
    __syncthreads();

    float c0s = 0.f, c1s = 0.f;   // rec cell states

    for (int w = 0; w < NWINS; ++w) {
        if (is_rec) {
            // ---------------- 8 recurrence steps ----------------
#pragma unroll
            for (int i = 0; i < 8; ++i) {
                const int t = w * WIN + i;
                const int slot = t & (RING - 1);
                float xa0 = XGR[slot * NG + ga];
                float xb0 = XGR[slot * NG + gb];
                float xa1 = XGR[RING * NG + slot * NG + ga];
                float xb1 = XGR[RING * NG + slot * NG + gb];

                const ulonglong2* hv0 = (const ulonglong2*)(HS + (t & 1) * 128);
                const ulonglong2* hv1 = hv0 + 16;   // batch 1 (+64 floats)
                unsigned long long A0 = 0ull, A1 = 0ull, C0 = 0ull, C1 = 0ull;
                unsigned long long D0 = 0ull, D1 = 0ull, E0 = 0ull, E1 = 0ull;
#pragma unroll
                for (int j = 0; j < 16; ++j) {
                    ulonglong2 h20 = hv0[j];
                    ulonglong2 h21 = hv1[j];
                    A0 = ffma2(wa[j].x, h20.x, A0);
                    A1 = ffma2(wa[j].y, h20.y, A1);
                    C0 = ffma2(wb[j].x, h20.x, C0);
                    C1 = ffma2(wb[j].y, h20.y, C1);
                    D0 = ffma2(wa[j].x, h21.x, D0);
                    D1 = ffma2(wa[j].y, h21.y, D1);
                    E0 = ffma2(wb[j].x, h21.x, E0);
                    E1 = ffma2(wb[j].y, h21.y, E1);
                }
                float sa0 = xa0 + red2(A0) + red2(A1);
                float sb0 = xb0 + red2(C0) + red2(C1);
                float sa1 = xa1 + red2(D0) + red2(D1);
                float sb1 = xb1 + red2(E0) + red2(E1);

                float Aq0 = fmaf(0.5f, tanh_ap(0.5f * sa0), 0.5f);
                float Bv0 = fmaf(sc, tanh_ap(kb * sb0), off);
                float pr0 = Aq0 * Bv0;
                float sd0 = role ? Aq0 : pr0;
                float Aq1 = fmaf(0.5f, tanh_ap(0.5f * sa1), 0.5f);
                float Bv1 = fmaf(sc, tanh_ap(kb * sb1), off);
                float pr1 = Aq1 * Bv1;
                float sd1 = role ? Aq1 : pr1;

                float rv0 = __shfl_xor_sync(0xFFFFFFFFu, sd0, 1);
                float rv1 = __shfl_xor_sync(0xFFFFFFFFu, sd1, 1);

                float cm0 = role ? Aq0 : rv0, cd0 = role ? rv0 : pr0;
                float cm1 = role ? Aq1 : rv1, cd1 = role ? rv1 : pr1;
                c0s = fmaf(cm0, c0s, cd0);
                c1s = fmaf(cm1, c1s, cd1);
                float th0 = tanh_ap(c0s);
                float th1 = tanh_ap(c1s);
                if (role) {
                    HS[((t + 1) & 1) * 128 + u]      = Bv0 * th0;
                    HS[((t + 1) & 1) * 128 + 64 + u] = Bv1 * th1;
                }
                asm volatile("bar.sync 1, 128;");
            }
        } else {
            // ---------------- producer ----------------
            const int wl = w + 4;          // window to stage
            const int wc = w + 3;          // window to compute
            float4 r0, r1;
            if (wl < NWINS) {
                int idx0 = pt, idx1 = pt + 128;
                int bb0 = idx0 >> 7, tq0 = (idx0 & 127) >> 4, q0 = idx0 & 15;
                int bb1 = idx1 >> 7, tq1 = (idx1 & 127) >> 4, q1 = idx1 & 15;
                r0 = ((const float4*)(x + ((size_t)(b0 + bb0) * TT
                                           + wl * WIN + tq0) * DD))[q0];
                r1 = ((const float4*)(x + ((size_t)(b0 + bb1) * TT
                                           + wl * WIN + tq1) * DD))[q1];
            }
            if (wc < NWINS) {
                const float* xw = XST + (wc & 3) * (2 * WIN * DD);
#pragma unroll
                for (int bb = 0; bb < 2; ++bb) {
                    unsigned long long aa[8], ab[8];
#pragma unroll
                    for (int i = 0; i < 8; ++i) { aa[i] = 0ull; ab[i] = 0ull; }
#pragma unroll
                    for (int j = 0; j < 16; ++j) {
                        ulonglong2 wja = wpa[j], wjb = wpb[j];
#pragma unroll
                        for (int i = 0; i < 8; ++i) {
                            ulonglong2 xv = *(const ulonglong2*)(xw
                                            + bb * WIN * DD + i * DD + j * 4);
                            aa[i] = ffma2(wja.x, xv.x, aa[i]);
                            aa[i] = ffma2(wja.y, xv.y, aa[i]);
                            ab[i] = ffma2(wjb.x, xv.x, ab[i]);
                            ab[i] = ffma2(wjb.y, xv.y, ab[i]);
                        }
                    }
#pragma unroll
                    for (int i = 0; i < 8; ++i) {
                        int slot = (wc * WIN + i) & (RING - 1);
                        XGR[bb * (RING * NG) + slot * NG + pga] = bpa + red2(aa[i]);
                        XGR[bb * (RING * NG) + slot * NG + pgb] = bpb + red2(ab[i]);
                    }
                }
            }
            if (wl < NWINS) {   // stage into slot wl&3 == w&3 (window w's x is dead)
                float4* dst = (float4*)(XST + (wl & 3) * (2 * WIN * DD));
                dst[pt]       = r0;
                dst[pt + 128] = r1;
            }
        }
        __syncthreads();
    }

    // ---- final FC: out[b, o] = h_last . fc_w[o] + fc_b[o] ----
    if (tid < 16) {
        int bb = tid >> 3, o = tid & 7;
        const float* hfin = HS + (TT & 1) * 128 + bb * 64;
        float s = fc_b[o];
#pragma unroll
        for (int k = 0; k < HH; ++k) s += hfin[k] * fc_w[o * HH + k];
        out[(b0 + bb) * 8 + o] = s;
    }
}

extern "C" void kernel_launch(void* const* d_in, const int* in_sizes, int n_in,
                              void* d_out, int out_size) {
    const float* x    = (const float*)d_in[0];
    const float* w_ih = (const float*)d_in[1];
    const float* w_hh = (const float*)d_in[2];
    const float* b_ih = (const float*)d_in[3];
    const float* b_hh = (const float*)d_in[4];
    const float* fc_w = (const float*)d_in[5];
    const float* fc_b = (const float*)d_in[6];
    float* out = (float*)d_out;

    const int B = in_sizes[0] / (TT * DD);   // 256

    static int attr_done = 0;
    if (!attr_done) {
        cudaFuncSetAttribute(lstm_ws,
                             cudaFuncAttributeMaxDynamicSharedMemorySize,
                             SMEM_BYTES);
        attr_done = 1;
    }
    lstm_ws<<<B / 2, 256, SMEM_BYTES>>>(x, w_ih, w_hh, b_ih, b_hh,
                                        fc_w, fc_b, out);
}